// round 16
// baseline (speedup 1.0000x reference)
#include <cuda_runtime.h>
#include <cuda_bf16.h>
#include <cuda_fp16.h>
#include <cstdint>

#define B_  4
#define S_  2048
#define D_  1024
#define M1  (B_ * S_)
#define NCAND 32
#define CBUF  64
#define CWIN  46.0f

typedef __nv_bfloat16 bf16;

// ---------------------------------------------------------------------------
// Scratch (__device__ globals; no allocation allowed)
// ---------------------------------------------------------------------------
__device__ __align__(256) bf16   g_Xhi[(size_t)M1 * D_];
__device__ __align__(256) bf16   g_Xlo[(size_t)M1 * D_];
__device__ __align__(256) __half g_Xh [(size_t)M1 * D_];
__device__ __align__(256) bf16   g_Whi[(size_t)D_ * D_];
__device__ __align__(256) bf16   g_Wlo[(size_t)D_ * D_];
__device__ __align__(256) __half g_Wh [(size_t)D_ * D_];
__device__ __align__(256) bf16   g_Qb [(size_t)M1 * D_];   // Q 1-pass, bf16
__device__ __align__(256) __half g_Vh [(size_t)M1 * D_];   // V fp16 [m][d]
__device__ __align__(256) float  g_Qc [(size_t)M1 * D_];   // exact Q, compact
__device__ int   g_nfix;
__device__ int   g_fixrows[(size_t)B_ * S_];
__device__ int   g_slot   [(size_t)B_ * S_];
__device__ int   g_cnt [(size_t)B_ * S_];
__device__ int   g_cand[(size_t)B_ * S_ * NCAND];
__device__ int   g_ccnt[(size_t)B_ * S_];
__device__ int   g_ccol[(size_t)B_ * S_ * CBUF];
__device__ float g_clog[(size_t)B_ * S_ * CBUF];
__device__ float g_Afallback[(size_t)B_ * S_ * S_];

// ---------------------------------------------------------------------------
// Baseline-PTX primitives
// ---------------------------------------------------------------------------
__device__ __forceinline__ uint32_t smem_u32(const void* p) {
    uint32_t a;
    asm("{ .reg .u64 t; cvta.to.shared.u64 t, %1; cvt.u32.u64 %0, t; }" : "=r"(a) : "l"(p));
    return a;
}
#define CPA(dst, src)  asm volatile("cp.async.cg.shared.global [%0], [%1], 16;\n" :: "r"(dst), "l"(src))
#define CP_COMMIT()    asm volatile("cp.async.commit_group;\n" ::: "memory")
#define CP_WAIT1()     asm volatile("cp.async.wait_group 1;\n" ::: "memory")
#define CP_WAIT0()     asm volatile("cp.async.wait_group 0;\n" ::: "memory")

__device__ __forceinline__ void ldsm4(uint32_t r[4], uint32_t a) {
    asm volatile("ldmatrix.sync.aligned.m8n8.x4.shared.b16 {%0,%1,%2,%3}, [%4];\n"
                 : "=r"(r[0]), "=r"(r[1]), "=r"(r[2]), "=r"(r[3]) : "r"(a));
}
__device__ __forceinline__ void mma_bf16(float* c, const uint32_t a[4], uint32_t b0, uint32_t b1) {
    asm volatile("mma.sync.aligned.m16n8k16.row.col.f32.bf16.bf16.f32 "
                 "{%0,%1,%2,%3}, {%4,%5,%6,%7}, {%8,%9}, {%0,%1,%2,%3};\n"
                 : "+f"(c[0]), "+f"(c[1]), "+f"(c[2]), "+f"(c[3])
                 : "r"(a[0]), "r"(a[1]), "r"(a[2]), "r"(a[3]), "r"(b0), "r"(b1));
}
__device__ __forceinline__ void mma_f16(float* c, const uint32_t a[4], uint32_t b0, uint32_t b1) {
    asm volatile("mma.sync.aligned.m16n8k16.row.col.f32.f16.f16.f32 "
                 "{%0,%1,%2,%3}, {%4,%5,%6,%7}, {%8,%9}, {%0,%1,%2,%3};\n"
                 : "+f"(c[0]), "+f"(c[1]), "+f"(c[2]), "+f"(c[3])
                 : "r"(a[0]), "r"(a[1]), "r"(a[2]), "r"(a[3]), "r"(b0), "r"(b1));
}
__device__ __forceinline__ void split_bf16(float v, bf16& h, bf16& l) {
    h = __float2bfloat16_rn(v);
    l = __float2bfloat16_rn(v - __bfloat162float(h));
}

// ---------------------------------------------------------------------------
// Tile loaders: 128 threads. K-major [128 rows][32 elems], smem rows 80B.
// ---------------------------------------------------------------------------
__device__ __forceinline__ void cpa_k(uint32_t sdst, const void* g, int ldbytes, int tid) {
#pragma unroll
    for (int i = 0; i < 4; i++) {
        int u = tid + i * 128;
        int r = u >> 2, c = u & 3;
        CPA(sdst + r * 80 + c * 16, (const char*)g + (size_t)r * ldbytes + c * 16);
    }
}
// Indirect-row variant: row r comes from sidx[r] (smem table)
__device__ __forceinline__ void cpa_ki(uint32_t sdst, const bf16* base,
                                       const int* sidx, int ko, int tid) {
#pragma unroll
    for (int i = 0; i < 4; i++) {
        int u = tid + i * 128;
        int r = u >> 2, c = u & 3;
        CPA(sdst + r * 80 + c * 16, base + (size_t)sidx[r] * D_ + ko + c * 8);
    }
}
__device__ __forceinline__ void ld4frag(uint32_t base, uint32_t r[4][4]) {
#pragma unroll
    for (int i = 0; i < 4; i++) ldsm4(r[i], base + i * 1280);
}
__device__ __forceinline__ void ldF64(uint32_t r[4][4], uint32_t base, int w, int lane, int ks) {
    const int row = lane & 15;
    const int ch  = (lane >> 4) + ks * 2;
    ld4frag(base + (w * 64 + row) * 80 + ch * 16, r);
}
__device__ __forceinline__ void mmas_bf16(float c[4][8][4], uint32_t a[4][4], uint32_t b[4][4]) {
#pragma unroll
    for (int mi = 0; mi < 4; mi++)
#pragma unroll
        for (int nj = 0; nj < 4; nj++) {
            mma_bf16(c[mi][2 * nj],     a[mi], b[nj][0], b[nj][2]);
            mma_bf16(c[mi][2 * nj + 1], a[mi], b[nj][1], b[nj][3]);
        }
}
__device__ __forceinline__ void mmas_f16(float c[4][8][4], uint32_t a[4][4], uint32_t b[4][4]) {
#pragma unroll
    for (int mi = 0; mi < 4; mi++)
#pragma unroll
        for (int nj = 0; nj < 4; nj++) {
            mma_f16(c[mi][2 * nj],     a[mi], b[nj][0], b[nj][2]);
            mma_f16(c[mi][2 * nj + 1], a[mi], b[nj][1], b[nj][3]);
        }
}

#define PIPE2_BOTTOM(LOADI, it, nit, STGB)                        \
    do {                                                          \
        if ((it) + 1 < (nit)) {                                   \
            __syncthreads();                                      \
            const bool more = ((it) + 2 < (nit));                 \
            if (more) { LOADI(sb + ((it) & 1) * (STGB), (it) + 2); } \
            if (more) { CP_WAIT1(); } else { CP_WAIT0(); }        \
            __syncthreads();                                      \
        }                                                         \
    } while (0)

// ---------------------------------------------------------------------------
// hi/lo 3-pass GEMM pieces (used by k_qfix)
// ---------------------------------------------------------------------------
#define HL_ALO 10240
#define HL_BHI 20480
#define HL_BLO 30720
#define HL_STG 40960
#define SMEM_HILO (2 * HL_STG)

__device__ __forceinline__ void kstep_hilo(uint32_t stg, int ks, int lane,
                                           int wm, int wn, float c[4][8][4]) {
    uint32_t ah[4][4], bh[4][4], t[4][4];
    ldF64(ah, stg, wm, lane, ks);
    ldF64(bh, stg + HL_BHI, wn, lane, ks);
    mmas_bf16(c, ah, bh);
    ldF64(t, stg + HL_BLO, wn, lane, ks);
    mmas_bf16(c, ah, t);
    ldF64(t, stg + HL_ALO, wm, lane, ks);
    mmas_bf16(c, t, bh);
}

// ---------------------------------------------------------------------------
// single-pass GEMM (B K-major): CTA 128x128, BK=64. bf16 or fp16.
// ---------------------------------------------------------------------------
#define NT_STG  40960
#define SMEM_NT (2 * NT_STG)

template<bool BF>
__device__ __forceinline__ void gemm_1p(const void* A_, int lda, const void* B_v, int ldb,
                                        int nit, uint32_t sb, int tid, float c[4][8][4]) {
    const int lane = tid & 31, wid = tid >> 5;
    const int wm = wid >> 1, wn = wid & 1;
    const int la = lda * 2, lb = ldb * 2;
    const char* Ap = (const char*)A_;
    const char* Bp = (const char*)B_v;
#define NT_LOADI(saddr, itn)                                      \
    do {                                                          \
        const int ko_ = (itn) * 64 * 2;                           \
        cpa_k((saddr),          Ap + ko_,      la, tid);          \
        cpa_k((saddr) + 10240,  Ap + ko_ + 64, la, tid);          \
        cpa_k((saddr) + 20480,  Bp + ko_,      lb, tid);          \
        cpa_k((saddr) + 30720,  Bp + ko_ + 64, lb, tid);          \
        CP_COMMIT();                                              \
    } while (0)
    NT_LOADI(sb, 0);
    if (nit > 1) { NT_LOADI(sb + NT_STG, 1); CP_WAIT1(); }
    else         { CP_WAIT0(); }
    __syncthreads();
    for (int it = 0; it < nit; it++) {
        const uint32_t stg = sb + (it & 1) * NT_STG;
#pragma unroll
        for (int k4 = 0; k4 < 4; k4++) {
            const int sub = k4 >> 1, ks = k4 & 1;
            uint32_t ah[4][4], bh[4][4];
            ldF64(ah, stg + sub * 10240, wm, lane, ks);
            ldF64(bh, stg + 20480 + sub * 10240, wn, lane, ks);
            if (BF) mmas_bf16(c, ah, bh);
            else    mmas_f16 (c, ah, bh);
        }
        PIPE2_BOTTOM(NT_LOADI, it, nit, NT_STG);
    }
#undef NT_LOADI
}

// ---------------------------------------------------------------------------
// Conversions (vectorized float4). Also zeroes per-row counters + g_nfix.
// ---------------------------------------------------------------------------
__global__ void k_cvtX(const float4* __restrict__ x, int n4) {
    const int gid = blockIdx.x * 256 + threadIdx.x;
    if (gid == 0) g_nfix = 0;
    if (gid < M1) g_ccnt[gid] = 0;
    int i = gid;
    const int stride = gridDim.x * 256;
    for (; i < n4; i += stride) {
        float4 v = x[i];
        bf16 h0, l0, h1, l1, h2, l2, h3, l3;
        split_bf16(v.x, h0, l0); split_bf16(v.y, h1, l1);
        split_bf16(v.z, h2, l2); split_bf16(v.w, h3, l3);
        uint2 hh, ll;
        hh.x = ((uint32_t)*(uint16_t*)&h1 << 16) | *(uint16_t*)&h0;
        hh.y = ((uint32_t)*(uint16_t*)&h3 << 16) | *(uint16_t*)&h2;
        ll.x = ((uint32_t)*(uint16_t*)&l1 << 16) | *(uint16_t*)&l0;
        ll.y = ((uint32_t)*(uint16_t*)&l3 << 16) | *(uint16_t*)&l2;
        *(uint2*)(g_Xhi + (size_t)i * 4) = hh;
        *(uint2*)(g_Xlo + (size_t)i * 4) = ll;
        __half2 f01 = __floats2half2_rn(v.x, v.y);
        __half2 f23 = __floats2half2_rn(v.z, v.w);
        uint2 ff; ff.x = *(uint32_t*)&f01; ff.y = *(uint32_t*)&f23;
        *(uint2*)(g_Xh + (size_t)i * 4) = ff;
    }
}
__global__ void k_cvtW(const float4* __restrict__ wqk, const float4* __restrict__ wov, int n4) {
    int i = blockIdx.x * 256 + threadIdx.x;
    const int stride = gridDim.x * 256;
    for (; i < n4; i += stride) {
        float4 v = wqk[i];
        bf16 h0, l0, h1, l1, h2, l2, h3, l3;
        split_bf16(v.x, h0, l0); split_bf16(v.y, h1, l1);
        split_bf16(v.z, h2, l2); split_bf16(v.w, h3, l3);
        uint2 hh, ll;
        hh.x = ((uint32_t)*(uint16_t*)&h1 << 16) | *(uint16_t*)&h0;
        hh.y = ((uint32_t)*(uint16_t*)&h3 << 16) | *(uint16_t*)&h2;
        ll.x = ((uint32_t)*(uint16_t*)&l1 << 16) | *(uint16_t*)&l0;
        ll.y = ((uint32_t)*(uint16_t*)&l3 << 16) | *(uint16_t*)&l2;
        *(uint2*)(g_Whi + (size_t)i * 4) = hh;
        *(uint2*)(g_Wlo + (size_t)i * 4) = ll;
        float4 w = wov[i];
        __half2 f01 = __floats2half2_rn(w.x, w.y);
        __half2 f23 = __floats2half2_rn(w.z, w.w);
        uint2 ff; ff.x = *(uint32_t*)&f01; ff.y = *(uint32_t*)&f23;
        *(uint2*)(g_Wh + (size_t)i * 4) = ff;
    }
}

// ---------------------------------------------------------------------------
// Merged Q+V kernel (z=0: Q 1-pass bf16 -> Qb; z=1: V 1-pass fp16)
// ---------------------------------------------------------------------------
__global__ __launch_bounds__(128, 2) void k_qv() {
    extern __shared__ __align__(1024) char smem[];
    const uint32_t sb = smem_u32(smem);
    const int tid = threadIdx.x;
    const int m0 = blockIdx.y * 128, n0 = blockIdx.x * 128;
    const int lane = tid & 31, wid = tid >> 5;
    const int wm = wid >> 1, wn = wid & 1;
    float c[4][8][4] = {};

    if (blockIdx.z == 0) {
        gemm_1p<true>(g_Xhi + (size_t)m0 * D_, D_, g_Whi + (size_t)n0 * D_, D_,
                      D_ / 64, sb, tid, c);
#pragma unroll
        for (int mi = 0; mi < 4; mi++) {
            const int r0 = m0 + wm * 64 + mi * 16 + (lane >> 2);
#pragma unroll
            for (int ni = 0; ni < 8; ni++) {
                const int gc = n0 + wn * 64 + ni * 8 + (lane & 3) * 2;
                const float* cc = c[mi][ni];
#pragma unroll
                for (int h = 0; h < 2; h++) {
                    const size_t idx = (size_t)(r0 + 8 * h) * D_ + gc;
                    __nv_bfloat162 qq;
                    qq.x = __float2bfloat16_rn(cc[2 * h]);
                    qq.y = __float2bfloat16_rn(cc[2 * h + 1]);
                    *(__nv_bfloat162*)(g_Qb + idx) = qq;
                }
            }
        }
    } else {
        gemm_1p<false>(g_Xh + (size_t)m0 * D_, D_, g_Wh + (size_t)n0 * D_, D_,
                       D_ / 64, sb, tid, c);
#pragma unroll
        for (int mi = 0; mi < 4; mi++) {
            const int r0 = m0 + wm * 64 + mi * 16 + (lane >> 2);
#pragma unroll
            for (int ni = 0; ni < 8; ni++) {
                const int gc = n0 + wn * 64 + ni * 8 + (lane & 3) * 2;
                const float* cc = c[mi][ni];
#pragma unroll
                for (int h = 0; h < 2; h++) {
                    const size_t idx = (size_t)(r0 + 8 * h) * D_ + gc;
                    *(__half2*)(g_Vh + idx) = __floats2half2_rn(cc[2 * h], cc[2 * h + 1]);
                }
            }
        }
    }
}

// ---------------------------------------------------------------------------
// Scores: 1-pass bf16 GEMM; accumulators spilled to SMEM tile, then low-reg
// candidate collection from SMEM. No dense A store (upper blocks write zeros).
// ---------------------------------------------------------------------------
#define ST_LD 132   // smem tile row stride (floats)

__global__ __launch_bounds__(128, 2) void k_scores(float* __restrict__ Aout) {
    const int b = blockIdx.z;
    const int m0 = blockIdx.y * 128, n0 = blockIdx.x * 128;
    const int tid = threadIdx.x;

    if (blockIdx.x > blockIdx.y) {
        float* Ab = Aout + (size_t)b * S_ * S_;
        const float4 z = make_float4(0.f, 0.f, 0.f, 0.f);
        for (int i = tid; i < 128 * 32; i += 128) {
            const int r = i >> 5, c4 = i & 31;
            ((float4*)(Ab + (size_t)(m0 + r) * S_ + n0))[c4] = z;
        }
        return;
    }

    extern __shared__ __align__(1024) char smem[];
    const uint32_t sb = smem_u32(smem);
    const size_t xb = (size_t)b * S_ * D_;
    float c[4][8][4] = {};
    gemm_1p<true>(g_Qb + xb + (size_t)m0 * D_, D_,
                  g_Xhi + xb + (size_t)n0 * D_, D_,
                  D_ / 64, sb, tid, c);

    const int lane = tid & 31, wid = tid >> 5;
    const int wm = wid >> 1, wn = wid & 1;
    const bool diag = (blockIdx.x == blockIdx.y);

    __syncthreads();                       // pipeline smem now dead -> reuse
    float* st = (float*)smem;              // [128][ST_LD]

    // single pass: dump accumulators (x32) to smem; c dies here
#pragma unroll
    for (int mi = 0; mi < 4; mi++) {
#pragma unroll
        for (int h = 0; h < 2; h++) {
            const int rl = wm * 64 + mi * 16 + (lane >> 2) + 8 * h;
#pragma unroll
            for (int ni = 0; ni < 8; ni++) {
                const int cl = wn * 64 + ni * 8 + (lane & 3) * 2;
                st[rl * ST_LD + cl]     = c[mi][ni][2 * h]     * 32.0f;
                st[rl * ST_LD + cl + 1] = c[mi][ni][2 * h + 1] * 32.0f;
            }
        }
    }
    __syncthreads();

    // low-register collection: each warp takes rows wid, wid+4, ...
    for (int rl = wid; rl < 128; rl += 4) {
        const int rg = m0 + rl;
        const int rowg = b * S_ + rg;
        float vv[4];
        float mx = -3.0e38f;
#pragma unroll
        for (int j = 0; j < 4; j++) {
            const int cl = j * 32 + lane;
            float v = st[rl * ST_LD + cl];
            if (diag && (n0 + cl) > rg) v = -3.0e38f;
            vv[j] = v;
            mx = fmaxf(mx, v);
        }
#pragma unroll
        for (int o = 16; o > 0; o >>= 1)
            mx = fmaxf(mx, __shfl_xor_sync(0xffffffffu, mx, o));
        const float thr = mx - CWIN;
#pragma unroll
        for (int j = 0; j < 4; j++) {
            if (vv[j] > thr) {
                const int cl = j * 32 + lane;
                int slot = atomicAdd(&g_ccnt[rowg], 1);
                if (slot < CBUF) {
                    g_ccol[(size_t)rowg * CBUF + slot] = n0 + cl;
                    g_clog[(size_t)rowg * CBUF + slot] = vv[j];
                }
            }
        }
    }
}

// ---------------------------------------------------------------------------
// k_merge: per row — zero A[0:diag_block_end), merge candidates (warp 0).
// ---------------------------------------------------------------------------
__global__ void k_merge(float* __restrict__ A) {
    const int s = blockIdx.x, b = blockIdx.y;
    const int rowi = b * S_ + s;
    const int tid = threadIdx.x, lane = tid & 31, warp = tid >> 5;

    const int blkend4 = (((s >> 7) + 1) << 7) >> 2;
    float4* row = (float4*)(A + (size_t)rowi * S_);
    const float4 z = make_float4(0.f, 0.f, 0.f, 0.f);
    for (int j = tid; j < blkend4; j += 256) row[j] = z;

    if (warp != 0) return;
    const int cntr = g_ccnt[rowi];
    if (cntr > CBUF) {
        if (lane == 0) {
            g_cnt[rowi] = 255;
            int sl = atomicAdd(&g_nfix, 1);
            g_fixrows[sl] = rowi; g_slot[rowi] = sl;
        }
        return;
    }
    float l0 = -3.0e38f, l1 = -3.0e38f;
    int c0 = 0, c1 = 0;
    if (lane < cntr)      { c0 = g_ccol[(size_t)rowi * CBUF + lane];      l0 = g_clog[(size_t)rowi * CBUF + lane]; }
    if (lane + 32 < cntr) { c1 = g_ccol[(size_t)rowi * CBUF + lane + 32]; l1 = g_clog[(size_t)rowi * CBUF + lane + 32]; }
    float m = fmaxf(l0, l1);
#pragma unroll
    for (int o = 16; o > 0; o >>= 1) m = fmaxf(m, __shfl_xor_sync(0xffffffffu, m, o));
    const float thr = m - CWIN;
    const unsigned b0 = __ballot_sync(0xffffffffu, l0 > thr);
    const unsigned b1 = __ballot_sync(0xffffffffu, l1 > thr);
    const int n0 = __popc(b0);
    const int hits = n0 + __popc(b1);
    if (hits > NCAND) {
        if (lane == 0) {
            g_cnt[rowi] = 255;
            int sl = atomicAdd(&g_nfix, 1);
            g_fixrows[sl] = rowi; g_slot[rowi] = sl;
        }
        return;
    }
    if (l0 > thr) g_cand[(size_t)rowi * NCAND + __popc(b0 & ((1u << lane) - 1))] = c0;
    if (l1 > thr) g_cand[(size_t)rowi * NCAND + n0 + __popc(b1 & ((1u << lane) - 1))] = c1;
    if (lane == 0) {
        g_cnt[rowi] = hits;
        if (hits > 1) {
            int sl = atomicAdd(&g_nfix, 1);
            g_fixrows[sl] = rowi; g_slot[rowi] = sl;
        }
    }
}

// ---------------------------------------------------------------------------
// Exact Q for flagged rows: 3-pass hilo GEMM with indirect A rows -> g_Qc.
// ---------------------------------------------------------------------------
__global__ __launch_bounds__(128, 2) void k_qfix() {
    const int m0 = blockIdx.y * 128;
    const int nfix = g_nfix;
    if (m0 >= nfix) return;
    extern __shared__ __align__(1024) char smem[];
    __shared__ int sidx[128];
    const uint32_t sb = smem_u32(smem);
    const int tid = threadIdx.x;
    const int n0 = blockIdx.x * 128;
    if (tid < 128) sidx[tid] = (m0 + tid < nfix) ? g_fixrows[m0 + tid] : 0;
    __syncthreads();

    const bf16* Bh = g_Whi + (size_t)n0 * D_;
    const bf16* Bl = g_Wlo + (size_t)n0 * D_;
    const int lb = D_ * 2;
    const int lane = tid & 31, wid = tid >> 5;
    const int wm = wid >> 1, wn = wid & 1;
    float c[4][8][4] = {};

#define HLX_LOADI(saddr, itn)                                     \
    do {                                                          \
        const int ko_ = (itn) * 32;                               \
        cpa_ki((saddr),          g_Xhi, sidx, ko_, tid);          \
        cpa_ki((saddr) + HL_ALO, g_Xlo, sidx, ko_, tid);          \
        cpa_k ((saddr) + HL_BHI, Bh + ko_, lb, tid);              \
        cpa_k ((saddr) + HL_BLO, Bl + ko_, lb, tid);              \
        CP_COMMIT();                                              \
    } while (0)

    const int nit = D_ / 32;
    HLX_LOADI(sb, 0);
    HLX_LOADI(sb + HL_STG, 1);
    CP_WAIT1();
    __syncthreads();
    for (int it = 0; it < nit; it++) {
        const uint32_t stg = sb + (it & 1) * HL_STG;
        kstep_hilo(stg, 0, lane, wm, wn, c);
        kstep_hilo(stg, 1, lane, wm, wn, c);
        PIPE2_BOTTOM(HLX_LOADI, it, nit, HL_STG);
    }
#undef HLX_LOADI

#pragma unroll
    for (int mi = 0; mi < 4; mi++) {
        const int r0 = m0 + wm * 64 + mi * 16 + (lane >> 2);
#pragma unroll
        for (int ni = 0; ni < 8; ni++) {
            const int gc = n0 + wn * 64 + ni * 8 + (lane & 3) * 2;
            const float* cc = c[mi][ni];
#pragma unroll
            for (int h = 0; h < 2; h++) {
                const size_t idx = (size_t)(r0 + 8 * h) * D_ + gc;
                *(float2*)(g_Qc + idx) = make_float2(cc[2 * h], cc[2 * h + 1]);
            }
        }
    }
}

// ---------------------------------------------------------------------------
// k_finish: exact softmax for flagged rows + out = X + A.V, all in one pass.
// ---------------------------------------------------------------------------
__global__ void k_finish(const float* __restrict__ X, float* __restrict__ Yout,
                         float* __restrict__ Aout) {
    const int s = blockIdx.x, b = blockIdx.y;
    const int rowi = b * S_ + s;
    const int cnt = g_cnt[rowi];
    const int tid = threadIdx.x, lane = tid & 31, warp = tid >> 5;
    const size_t xoff = (size_t)rowi * D_;
    float* Arow = Aout + (size_t)rowi * S_;
    const int* crow = g_cand + (size_t)rowi * NCAND;

    float4 x4 = ((const float4*)(X + xoff))[tid];

    if (cnt <= 1) {
        const int t = crow[0];
        if (tid == 0) Arow[t] = 1.0f;
        const __half2* vr = (const __half2*)(g_Vh + ((size_t)b * S_ + t) * D_) + tid * 2;
        float2 p0 = __half22float2(vr[0]);
        float2 p1 = __half22float2(vr[1]);
        float4 o = make_float4(x4.x + p0.x, x4.y + p0.y, x4.z + p1.x, x4.w + p1.y);
        ((float4*)(Yout + xoff))[tid] = o;
        return;
    }

    __shared__ float qrow[D_];
    __shared__ float av[NCAND];
    __shared__ float red[8];
    const int slot = g_slot[rowi];
    ((float4*)qrow)[tid] = ((const float4*)(g_Qc + (size_t)slot * D_))[tid];
    __syncthreads();
    const float* Xb = X + (size_t)b * S_ * D_;

    float y0 = 0.f, y1 = 0.f, y2 = 0.f, y3 = 0.f;

    if (cnt != 255) {
        for (int ci = warp; ci < cnt; ci += 8) {
            const float* xr = Xb + (size_t)crow[ci] * D_;
            float d = 0.f;
            for (int k = lane; k < D_; k += 32) d += qrow[k] * xr[k];
#pragma unroll
            for (int o = 16; o > 0; o >>= 1) d += __shfl_xor_sync(0xffffffffu, d, o);
            if (lane == 0) av[ci] = d * 32.0f;
        }
        __syncthreads();
        if (tid == 0) {
            float mm = -3.0e38f;
            for (int ci = 0; ci < cnt; ci++) mm = fmaxf(mm, av[ci]);
            float Z = 0.f;
            for (int ci = 0; ci < cnt; ci++) { av[ci] = expf(av[ci] - mm); Z += av[ci]; }
            const float inv = 1.0f / Z;
            for (int ci = 0; ci < cnt; ci++) {
                av[ci] *= inv;
                Arow[crow[ci]] = av[ci];
            }
        }
        __syncthreads();
        for (int ci = 0; ci < cnt; ci++) {
            const float a = av[ci];
            const __half2* vr = (const __half2*)(g_Vh + ((size_t)b * S_ + crow[ci]) * D_) + tid * 2;
            float2 p0 = __half22float2(vr[0]);
            float2 p1 = __half22float2(vr[1]);
            y0 += a * p0.x; y1 += a * p0.y; y2 += a * p1.x; y3 += a * p1.y;
        }
    } else {
        const int len = s + 1;
        for (int t = warp; t < len; t += 8) {
            const float* xr = Xb + (size_t)t * D_;
            float d = 0.f;
            for (int k = lane; k < D_; k += 32) d += qrow[k] * xr[k];
#pragma unroll
            for (int o = 16; o > 0; o >>= 1) d += __shfl_xor_sync(0xffffffffu, d, o);
            if (lane == 0) Arow[t] = d * 32.0f;
        }
        __syncthreads();
        float mm = -3.0e38f;
        for (int j = tid; j < len; j += 256) mm = fmaxf(mm, Arow[j]);
#pragma unroll
        for (int o = 16; o > 0; o >>= 1) mm = fmaxf(mm, __shfl_xor_sync(0xffffffffu, mm, o));
        if (lane == 0) red[warp] = mm;
        __syncthreads();
        mm = red[lane & 7];
#pragma unroll
        for (int o = 4; o > 0; o >>= 1) mm = fmaxf(mm, __shfl_xor_sync(0xffffffffu, mm, o));
        float Z = 0.f;
        for (int j = tid; j < len; j += 256) Z += expf(Arow[j] - mm);
#pragma unroll
        for (int o = 16; o > 0; o >>= 1) Z += __shfl_xor_sync(0xffffffffu, Z, o);
        if (lane == 0) red[warp] = Z;
        __syncthreads();
        Z = red[lane & 7];
#pragma unroll
        for (int o = 4; o > 0; o >>= 1) Z += __shfl_xor_sync(0xffffffffu, Z, o);
        const float inv = 1.0f / Z;
        __syncthreads();
        for (int j = tid; j < len; j += 256) Arow[j] = expf(Arow[j] - mm) * inv;
        __syncthreads();
        for (int t = 0; t < len; t++) {
            const float a = Arow[t];
            if (a > 1e-30f) {
                const __half2* vr = (const __half2*)(g_Vh + ((size_t)b * S_ + t) * D_) + tid * 2;
                float2 p0 = __half22float2(vr[0]);
                float2 p1 = __half22float2(vr[1]);
                y0 += a * p0.x; y1 += a * p0.y; y2 += a * p1.x; y3 += a * p1.y;
            }
        }
    }
    float4 o = make_float4(x4.x + y0, x4.y + y1, x4.z + y2, x4.w + y3);
    ((float4*)(Yout + xoff))[tid] = o;
}

// ---------------------------------------------------------------------------
extern "C" void kernel_launch(void* const* d_in, const int* in_sizes, int n_in,
                              void* d_out, int out_size) {
    const float* X   = (const float*)d_in[0];
    const float* WQK = (const float*)d_in[2];
    const float* WOV = (const float*)d_in[3];
    float* out = (float*)d_out;

    const size_t nY = (size_t)M1 * D_;
    const size_t nA = (size_t)B_ * S_ * S_;
    float* Aout;
    if ((size_t)out_size >= nY + nA) {
        Aout = out + nY;
    } else {
        void* p = nullptr;
        cudaGetSymbolAddress(&p, g_Afallback);
        Aout = (float*)p;
    }

    static bool attrs_set = false;
    if (!attrs_set) {
        cudaFuncSetAttribute(k_qv,     cudaFuncAttributeMaxDynamicSharedMemorySize, SMEM_NT);
        cudaFuncSetAttribute(k_scores, cudaFuncAttributeMaxDynamicSharedMemorySize, SMEM_NT);
        cudaFuncSetAttribute(k_qfix,   cudaFuncAttributeMaxDynamicSharedMemorySize, SMEM_HILO);
        attrs_set = true;
    }

    // 1) conversions (+ counter resets)
    k_cvtX<<<512, 256>>>((const float4*)X, M1 * D_ / 4);
    k_cvtW<<<256, 256>>>((const float4*)WQK, (const float4*)WOV, D_ * D_ / 4);
    // 2) Q (1-pass bf16) and V (1-pass fp16)
    k_qv<<<dim3(D_ / 128, M1 / 128, 2), 128, SMEM_NT>>>();
    // 3) scores GEMM + smem-staged candidate collection; upper-tri zeros
    k_scores<<<dim3(S_ / 128, S_ / 128, B_), 128, SMEM_NT>>>(Aout);
    // 4) merge candidates per row + zero lower A range
    k_merge<<<dim3(S_, B_), 256>>>(Aout);
    // 5) exact Q for flagged rows (indirect 3-pass GEMM)
    k_qfix<<<dim3(D_ / 128, M1 / 128), 128, SMEM_HILO>>>();
    // 6) exact softmax + out = X + A.V in one pass
    k_finish<<<dim3(S_, B_), 256>>>(X, out, Aout);
}

// round 17
// speedup vs baseline: 1.0917x; 1.0917x over previous
#include <cuda_runtime.h>
#include <cuda_bf16.h>
#include <cuda_fp16.h>
#include <cstdint>

#define B_  4
#define S_  2048
#define D_  1024
#define M1  (B_ * S_)
#define NCAND 32
#define CWIN  46.0f

typedef __nv_bfloat16 bf16;

// ---------------------------------------------------------------------------
// Scratch (__device__ globals; no allocation allowed)
// ---------------------------------------------------------------------------
__device__ __align__(256) bf16   g_Xhi[(size_t)M1 * D_];
__device__ __align__(256) bf16   g_Xlo[(size_t)M1 * D_];
__device__ __align__(256) __half g_Xh [(size_t)M1 * D_];
__device__ __align__(256) bf16   g_Whi[(size_t)D_ * D_];
__device__ __align__(256) bf16   g_Wlo[(size_t)D_ * D_];
__device__ __align__(256) __half g_Wh [(size_t)D_ * D_];
__device__ __align__(256) bf16   g_Qb [(size_t)M1 * D_];    // Q 1-pass, bf16
__device__ __align__(256) __half g_Vh [(size_t)M1 * D_];    // V fp16 [m][d]
__device__ __align__(256) float  g_Qc [(size_t)M1 * D_];    // exact Q, compact
__device__ __align__(256) __half g_Lh [(size_t)B_ * S_ * S_]; // fp16 logit scratch
__device__ int   g_nfix;
__device__ int   g_fixrows[(size_t)B_ * S_];
__device__ int   g_slot   [(size_t)B_ * S_];
__device__ int   g_cnt [(size_t)B_ * S_];
__device__ int   g_cand[(size_t)B_ * S_ * NCAND];
__device__ float g_Afallback[(size_t)B_ * S_ * S_];

// ---------------------------------------------------------------------------
// Baseline-PTX primitives
// ---------------------------------------------------------------------------
__device__ __forceinline__ uint32_t smem_u32(const void* p) {
    uint32_t a;
    asm("{ .reg .u64 t; cvta.to.shared.u64 t, %1; cvt.u32.u64 %0, t; }" : "=r"(a) : "l"(p));
    return a;
}
#define CPA(dst, src)  asm volatile("cp.async.cg.shared.global [%0], [%1], 16;\n" :: "r"(dst), "l"(src))
#define CP_COMMIT()    asm volatile("cp.async.commit_group;\n" ::: "memory")
#define CP_WAIT1()     asm volatile("cp.async.wait_group 1;\n" ::: "memory")
#define CP_WAIT0()     asm volatile("cp.async.wait_group 0;\n" ::: "memory")

__device__ __forceinline__ void ldsm4(uint32_t r[4], uint32_t a) {
    asm volatile("ldmatrix.sync.aligned.m8n8.x4.shared.b16 {%0,%1,%2,%3}, [%4];\n"
                 : "=r"(r[0]), "=r"(r[1]), "=r"(r[2]), "=r"(r[3]) : "r"(a));
}
__device__ __forceinline__ void mma_bf16(float* c, const uint32_t a[4], uint32_t b0, uint32_t b1) {
    asm volatile("mma.sync.aligned.m16n8k16.row.col.f32.bf16.bf16.f32 "
                 "{%0,%1,%2,%3}, {%4,%5,%6,%7}, {%8,%9}, {%0,%1,%2,%3};\n"
                 : "+f"(c[0]), "+f"(c[1]), "+f"(c[2]), "+f"(c[3])
                 : "r"(a[0]), "r"(a[1]), "r"(a[2]), "r"(a[3]), "r"(b0), "r"(b1));
}
__device__ __forceinline__ void mma_f16(float* c, const uint32_t a[4], uint32_t b0, uint32_t b1) {
    asm volatile("mma.sync.aligned.m16n8k16.row.col.f32.f16.f16.f32 "
                 "{%0,%1,%2,%3}, {%4,%5,%6,%7}, {%8,%9}, {%0,%1,%2,%3};\n"
                 : "+f"(c[0]), "+f"(c[1]), "+f"(c[2]), "+f"(c[3])
                 : "r"(a[0]), "r"(a[1]), "r"(a[2]), "r"(a[3]), "r"(b0), "r"(b1));
}
__device__ __forceinline__ void split_bf16(float v, bf16& h, bf16& l) {
    h = __float2bfloat16_rn(v);
    l = __float2bfloat16_rn(v - __bfloat162float(h));
}

// ---------------------------------------------------------------------------
// Tile loaders: 128 threads. K-major [128 rows][32 elems], smem rows 80B.
// ---------------------------------------------------------------------------
__device__ __forceinline__ void cpa_k(uint32_t sdst, const void* g, int ldbytes, int tid) {
#pragma unroll
    for (int i = 0; i < 4; i++) {
        int u = tid + i * 128;
        int r = u >> 2, c = u & 3;
        CPA(sdst + r * 80 + c * 16, (const char*)g + (size_t)r * ldbytes + c * 16);
    }
}
// Indirect-row variant: row r comes from sidx[r] (smem table)
__device__ __forceinline__ void cpa_ki(uint32_t sdst, const bf16* base,
                                       const int* sidx, int ko, int tid) {
#pragma unroll
    for (int i = 0; i < 4; i++) {
        int u = tid + i * 128;
        int r = u >> 2, c = u & 3;
        CPA(sdst + r * 80 + c * 16, base + (size_t)sidx[r] * D_ + ko + c * 8);
    }
}
__device__ __forceinline__ void ld4frag(uint32_t base, uint32_t r[4][4]) {
#pragma unroll
    for (int i = 0; i < 4; i++) ldsm4(r[i], base + i * 1280);
}
__device__ __forceinline__ void ldF64(uint32_t r[4][4], uint32_t base, int w, int lane, int ks) {
    const int row = lane & 15;
    const int ch  = (lane >> 4) + ks * 2;
    ld4frag(base + (w * 64 + row) * 80 + ch * 16, r);
}
__device__ __forceinline__ void mmas_bf16(float c[4][8][4], uint32_t a[4][4], uint32_t b[4][4]) {
#pragma unroll
    for (int mi = 0; mi < 4; mi++)
#pragma unroll
        for (int nj = 0; nj < 4; nj++) {
            mma_bf16(c[mi][2 * nj],     a[mi], b[nj][0], b[nj][2]);
            mma_bf16(c[mi][2 * nj + 1], a[mi], b[nj][1], b[nj][3]);
        }
}
__device__ __forceinline__ void mmas_f16(float c[4][8][4], uint32_t a[4][4], uint32_t b[4][4]) {
#pragma unroll
    for (int mi = 0; mi < 4; mi++)
#pragma unroll
        for (int nj = 0; nj < 4; nj++) {
            mma_f16(c[mi][2 * nj],     a[mi], b[nj][0], b[nj][2]);
            mma_f16(c[mi][2 * nj + 1], a[mi], b[nj][1], b[nj][3]);
        }
}

#define PIPE2_BOTTOM(LOADI, it, nit, STGB)                        \
    do {                                                          \
        if ((it) + 1 < (nit)) {                                   \
            __syncthreads();                                      \
            const bool more = ((it) + 2 < (nit));                 \
            if (more) { LOADI(sb + ((it) & 1) * (STGB), (it) + 2); } \
            if (more) { CP_WAIT1(); } else { CP_WAIT0(); }        \
            __syncthreads();                                      \
        }                                                         \
    } while (0)

// ---------------------------------------------------------------------------
// hi/lo 3-pass GEMM pieces (used by k_qfix)
// ---------------------------------------------------------------------------
#define HL_ALO 10240
#define HL_BHI 20480
#define HL_BLO 30720
#define HL_STG 40960
#define SMEM_HILO (2 * HL_STG)

__device__ __forceinline__ void kstep_hilo(uint32_t stg, int ks, int lane,
                                           int wm, int wn, float c[4][8][4]) {
    uint32_t ah[4][4], bh[4][4], t[4][4];
    ldF64(ah, stg, wm, lane, ks);
    ldF64(bh, stg + HL_BHI, wn, lane, ks);
    mmas_bf16(c, ah, bh);
    ldF64(t, stg + HL_BLO, wn, lane, ks);
    mmas_bf16(c, ah, t);
    ldF64(t, stg + HL_ALO, wm, lane, ks);
    mmas_bf16(c, t, bh);
}

// ---------------------------------------------------------------------------
// single-pass GEMM (B K-major): CTA 128x128, BK=64. bf16 or fp16.
// ---------------------------------------------------------------------------
#define NT_STG  40960
#define SMEM_NT (2 * NT_STG)

template<bool BF>
__device__ __forceinline__ void gemm_1p(const void* A_, int lda, const void* B_v, int ldb,
                                        int nit, uint32_t sb, int tid, float c[4][8][4]) {
    const int lane = tid & 31, wid = tid >> 5;
    const int wm = wid >> 1, wn = wid & 1;
    const int la = lda * 2, lb = ldb * 2;
    const char* Ap = (const char*)A_;
    const char* Bp = (const char*)B_v;
#define NT_LOADI(saddr, itn)                                      \
    do {                                                          \
        const int ko_ = (itn) * 64 * 2;                           \
        cpa_k((saddr),          Ap + ko_,      la, tid);          \
        cpa_k((saddr) + 10240,  Ap + ko_ + 64, la, tid);          \
        cpa_k((saddr) + 20480,  Bp + ko_,      lb, tid);          \
        cpa_k((saddr) + 30720,  Bp + ko_ + 64, lb, tid);          \
        CP_COMMIT();                                              \
    } while (0)
    NT_LOADI(sb, 0);
    if (nit > 1) { NT_LOADI(sb + NT_STG, 1); CP_WAIT1(); }
    else         { CP_WAIT0(); }
    __syncthreads();
    for (int it = 0; it < nit; it++) {
        const uint32_t stg = sb + (it & 1) * NT_STG;
#pragma unroll
        for (int k4 = 0; k4 < 4; k4++) {
            const int sub = k4 >> 1, ks = k4 & 1;
            uint32_t ah[4][4], bh[4][4];
            ldF64(ah, stg + sub * 10240, wm, lane, ks);
            ldF64(bh, stg + 20480 + sub * 10240, wn, lane, ks);
            if (BF) mmas_bf16(c, ah, bh);
            else    mmas_f16 (c, ah, bh);
        }
        PIPE2_BOTTOM(NT_LOADI, it, nit, NT_STG);
    }
#undef NT_LOADI
}

// ---------------------------------------------------------------------------
// Merged conversion: X -> (hi, lo, fp16); WQK -> (hi, lo); WOV -> fp16.
// ---------------------------------------------------------------------------
#define N4X (M1 * D_ / 4)
#define N4W (D_ * D_ / 4)

__global__ void k_cvt(const float4* __restrict__ x, const float4* __restrict__ wqk,
                      const float4* __restrict__ wov) {
    const int gid = blockIdx.x * 256 + threadIdx.x;
    if (gid == 0) g_nfix = 0;
    const int stride = gridDim.x * 256;
    for (int i = gid; i < N4X + N4W; i += stride) {
        if (i < N4X) {
            float4 v = x[i];
            bf16 h0, l0, h1, l1, h2, l2, h3, l3;
            split_bf16(v.x, h0, l0); split_bf16(v.y, h1, l1);
            split_bf16(v.z, h2, l2); split_bf16(v.w, h3, l3);
            uint2 hh, ll;
            hh.x = ((uint32_t)*(uint16_t*)&h1 << 16) | *(uint16_t*)&h0;
            hh.y = ((uint32_t)*(uint16_t*)&h3 << 16) | *(uint16_t*)&h2;
            ll.x = ((uint32_t)*(uint16_t*)&l1 << 16) | *(uint16_t*)&l0;
            ll.y = ((uint32_t)*(uint16_t*)&l3 << 16) | *(uint16_t*)&l2;
            *(uint2*)(g_Xhi + (size_t)i * 4) = hh;
            *(uint2*)(g_Xlo + (size_t)i * 4) = ll;
            __half2 f01 = __floats2half2_rn(v.x, v.y);
            __half2 f23 = __floats2half2_rn(v.z, v.w);
            uint2 ff; ff.x = *(uint32_t*)&f01; ff.y = *(uint32_t*)&f23;
            *(uint2*)(g_Xh + (size_t)i * 4) = ff;
        } else {
            const int j = i - N4X;
            float4 v = wqk[j];
            bf16 h0, l0, h1, l1, h2, l2, h3, l3;
            split_bf16(v.x, h0, l0); split_bf16(v.y, h1, l1);
            split_bf16(v.z, h2, l2); split_bf16(v.w, h3, l3);
            uint2 hh, ll;
            hh.x = ((uint32_t)*(uint16_t*)&h1 << 16) | *(uint16_t*)&h0;
            hh.y = ((uint32_t)*(uint16_t*)&h3 << 16) | *(uint16_t*)&h2;
            ll.x = ((uint32_t)*(uint16_t*)&l1 << 16) | *(uint16_t*)&l0;
            ll.y = ((uint32_t)*(uint16_t*)&l3 << 16) | *(uint16_t*)&l2;
            *(uint2*)(g_Whi + (size_t)j * 4) = hh;
            *(uint2*)(g_Wlo + (size_t)j * 4) = ll;
            float4 w = wov[j];
            __half2 f01 = __floats2half2_rn(w.x, w.y);
            __half2 f23 = __floats2half2_rn(w.z, w.w);
            uint2 ff; ff.x = *(uint32_t*)&f01; ff.y = *(uint32_t*)&f23;
            *(uint2*)(g_Wh + (size_t)j * 4) = ff;
        }
    }
}

// ---------------------------------------------------------------------------
// Merged Q+V kernel (z=0: Q 1-pass bf16 -> Qb; z=1: V 1-pass fp16)
// ---------------------------------------------------------------------------
__global__ __launch_bounds__(128, 2) void k_qv() {
    extern __shared__ __align__(1024) char smem[];
    const uint32_t sb = smem_u32(smem);
    const int tid = threadIdx.x;
    const int m0 = blockIdx.y * 128, n0 = blockIdx.x * 128;
    const int lane = tid & 31, wid = tid >> 5;
    const int wm = wid >> 1, wn = wid & 1;
    float c[4][8][4] = {};

    if (blockIdx.z == 0) {
        gemm_1p<true>(g_Xhi + (size_t)m0 * D_, D_, g_Whi + (size_t)n0 * D_, D_,
                      D_ / 64, sb, tid, c);
#pragma unroll
        for (int mi = 0; mi < 4; mi++) {
            const int r0 = m0 + wm * 64 + mi * 16 + (lane >> 2);
#pragma unroll
            for (int ni = 0; ni < 8; ni++) {
                const int gc = n0 + wn * 64 + ni * 8 + (lane & 3) * 2;
                const float* cc = c[mi][ni];
#pragma unroll
                for (int h = 0; h < 2; h++) {
                    const size_t idx = (size_t)(r0 + 8 * h) * D_ + gc;
                    __nv_bfloat162 qq;
                    qq.x = __float2bfloat16_rn(cc[2 * h]);
                    qq.y = __float2bfloat16_rn(cc[2 * h + 1]);
                    *(__nv_bfloat162*)(g_Qb + idx) = qq;
                }
            }
        }
    } else {
        gemm_1p<false>(g_Xh + (size_t)m0 * D_, D_, g_Wh + (size_t)n0 * D_, D_,
                       D_ / 64, sb, tid, c);
#pragma unroll
        for (int mi = 0; mi < 4; mi++) {
            const int r0 = m0 + wm * 64 + mi * 16 + (lane >> 2);
#pragma unroll
            for (int ni = 0; ni < 8; ni++) {
                const int gc = n0 + wn * 64 + ni * 8 + (lane & 3) * 2;
                const float* cc = c[mi][ni];
#pragma unroll
                for (int h = 0; h < 2; h++) {
                    const size_t idx = (size_t)(r0 + 8 * h) * D_ + gc;
                    *(__half2*)(g_Vh + idx) = __floats2half2_rn(cc[2 * h], cc[2 * h + 1]);
                }
            }
        }
    }
}

// ---------------------------------------------------------------------------
// Scores: 1-pass bf16 GEMM. Lower/diag blocks: fp16 logits -> g_Lh scratch AND
// fp32 zeros -> A tile. Upper blocks: zeros -> A tile only.
// ---------------------------------------------------------------------------
__global__ __launch_bounds__(128, 2) void k_scores(float* __restrict__ Aout) {
    const int b = blockIdx.z;
    const int m0 = blockIdx.y * 128, n0 = blockIdx.x * 128;
    const int tid = threadIdx.x;
    float* Ab = Aout + (size_t)b * S_ * S_;

    if (blockIdx.x > blockIdx.y) {
        const float4 z = make_float4(0.f, 0.f, 0.f, 0.f);
        for (int i = tid; i < 128 * 32; i += 128) {
            const int r = i >> 5, c4 = i & 31;
            ((float4*)(Ab + (size_t)(m0 + r) * S_ + n0))[c4] = z;
        }
        return;
    }

    extern __shared__ __align__(1024) char smem[];
    const uint32_t sb = smem_u32(smem);
    const size_t xb = (size_t)b * S_ * D_;
    float c[4][8][4] = {};
    gemm_1p<true>(g_Qb + xb + (size_t)m0 * D_, D_,
                  g_Xhi + xb + (size_t)n0 * D_, D_,
                  D_ / 64, sb, tid, c);

    const int lane = tid & 31, wid = tid >> 5;
    const int wm = wid >> 1, wn = wid & 1;
    __half* Lb = g_Lh + (size_t)b * S_ * S_;

    // fp16 logits to scratch (c dies here)
#pragma unroll
    for (int mi = 0; mi < 4; mi++) {
        const int r0 = m0 + wm * 64 + mi * 16 + (lane >> 2);
#pragma unroll
        for (int ni = 0; ni < 8; ni++) {
            const int gc = n0 + wn * 64 + ni * 8 + (lane & 3) * 2;
            const float* cc = c[mi][ni];
#pragma unroll
            for (int h = 0; h < 2; h++) {
                __half2 hv = __floats2half2_rn(cc[2 * h] * 32.0f, cc[2 * h + 1] * 32.0f);
                *(__half2*)(Lb + (size_t)(r0 + 8 * h) * S_ + gc) = hv;
            }
        }
    }
    // zero this CTA's A tile
    const float4 z = make_float4(0.f, 0.f, 0.f, 0.f);
    for (int i = tid; i < 128 * 32; i += 128) {
        const int r = i >> 5, c4 = i & 31;
        ((float4*)(Ab + (size_t)(m0 + r) * S_ + n0))[c4] = z;
    }
}

// ---------------------------------------------------------------------------
// Candidate finder: reads fp16 logit scratch over [0, diag-block-end);
// collects {j: l_j > max - CWIN}; flags rows with cnt>1. No A writes.
// ---------------------------------------------------------------------------
__global__ void k_softmax() {
    const int s = blockIdx.x, b = blockIdx.y;
    const int rowi = b * S_ + s;
    const __half* Lrow = g_Lh + (size_t)rowi * S_;
    const int len = s + 1;
    const int blkend = ((s >> 7) + 1) << 7;
    const int tid = threadIdx.x;
    const int lane = tid & 31, warp = tid >> 5;
    __shared__ float red[8];
    __shared__ int scnt;
    if (tid == 0) scnt = 0;

    float vv[8];
    float m = -3.0e38f;
#pragma unroll
    for (int it = 0; it < 2; it++) {
        const int j = (tid + it * 256) * 4;
        float f[4] = {-3.0e38f, -3.0e38f, -3.0e38f, -3.0e38f};
        if (j < blkend) {
            uint2 u = *(const uint2*)(Lrow + j);
            float2 p0 = __half22float2(*(__half2*)&u.x);
            float2 p1 = __half22float2(*(__half2*)&u.y);
            f[0] = (j + 0 < len) ? p0.x : -3.0e38f;
            f[1] = (j + 1 < len) ? p0.y : -3.0e38f;
            f[2] = (j + 2 < len) ? p1.x : -3.0e38f;
            f[3] = (j + 3 < len) ? p1.y : -3.0e38f;
        }
#pragma unroll
        for (int e = 0; e < 4; e++) {
            vv[it * 4 + e] = f[e];
            m = fmaxf(m, f[e]);
        }
    }
#pragma unroll
    for (int o = 16; o > 0; o >>= 1)
        m = fmaxf(m, __shfl_xor_sync(0xffffffffu, m, o));
    if (lane == 0) red[warp] = m;
    __syncthreads();
    m = red[lane & 7];
#pragma unroll
    for (int o = 4; o > 0; o >>= 1)
        m = fmaxf(m, __shfl_xor_sync(0xffffffffu, m, o));

    const float thr = m - CWIN;
    int* crow = g_cand + (size_t)rowi * NCAND;
#pragma unroll
    for (int it = 0; it < 2; it++) {
        const int j = (tid + it * 256) * 4;
#pragma unroll
        for (int e = 0; e < 4; e++) {
            if (vv[it * 4 + e] > thr) {
                int slot = atomicAdd(&scnt, 1);
                if (slot < NCAND) crow[slot] = j + e;
            }
        }
    }
    __syncthreads();
    if (tid == 0) {
        g_cnt[rowi] = (scnt <= NCAND) ? scnt : 255;
        if (scnt > 1) {
            int sl = atomicAdd(&g_nfix, 1);
            g_fixrows[sl] = rowi;
            g_slot[rowi] = sl;
        }
    }
}

// ---------------------------------------------------------------------------
// Exact Q for flagged rows: 3-pass hilo GEMM with indirect A rows -> g_Qc.
// ---------------------------------------------------------------------------
__global__ __launch_bounds__(128, 2) void k_qfix() {
    const int m0 = blockIdx.y * 128;
    const int nfix = g_nfix;
    if (m0 >= nfix) return;
    extern __shared__ __align__(1024) char smem[];
    __shared__ int sidx[128];
    const uint32_t sb = smem_u32(smem);
    const int tid = threadIdx.x;
    const int n0 = blockIdx.x * 128;
    if (tid < 128) sidx[tid] = (m0 + tid < nfix) ? g_fixrows[m0 + tid] : 0;
    __syncthreads();

    const bf16* Bh = g_Whi + (size_t)n0 * D_;
    const bf16* Bl = g_Wlo + (size_t)n0 * D_;
    const int lb = D_ * 2;
    const int lane = tid & 31, wid = tid >> 5;
    const int wm = wid >> 1, wn = wid & 1;
    float c[4][8][4] = {};

#define HLX_LOADI(saddr, itn)                                     \
    do {                                                          \
        const int ko_ = (itn) * 32;                               \
        cpa_ki((saddr),          g_Xhi, sidx, ko_, tid);          \
        cpa_ki((saddr) + HL_ALO, g_Xlo, sidx, ko_, tid);          \
        cpa_k ((saddr) + HL_BHI, Bh + ko_, lb, tid);              \
        cpa_k ((saddr) + HL_BLO, Bl + ko_, lb, tid);              \
        CP_COMMIT();                                              \
    } while (0)

    const int nit = D_ / 32;
    HLX_LOADI(sb, 0);
    HLX_LOADI(sb + HL_STG, 1);
    CP_WAIT1();
    __syncthreads();
    for (int it = 0; it < nit; it++) {
        const uint32_t stg = sb + (it & 1) * HL_STG;
        kstep_hilo(stg, 0, lane, wm, wn, c);
        kstep_hilo(stg, 1, lane, wm, wn, c);
        PIPE2_BOTTOM(HLX_LOADI, it, nit, HL_STG);
    }
#undef HLX_LOADI

#pragma unroll
    for (int mi = 0; mi < 4; mi++) {
        const int r0 = m0 + wm * 64 + mi * 16 + (lane >> 2);
#pragma unroll
        for (int ni = 0; ni < 8; ni++) {
            const int gc = n0 + wn * 64 + ni * 8 + (lane & 3) * 2;
            const float* cc = c[mi][ni];
#pragma unroll
            for (int h = 0; h < 2; h++) {
                const size_t idx = (size_t)(r0 + 8 * h) * D_ + gc;
                *(float2*)(g_Qc + idx) = make_float2(cc[2 * h], cc[2 * h + 1]);
            }
        }
    }
}

// ---------------------------------------------------------------------------
// k_finish: exact softmax for flagged rows + out = X + A.V, all in one pass.
// ---------------------------------------------------------------------------
__global__ void k_finish(const float* __restrict__ X, float* __restrict__ Yout,
                         float* __restrict__ Aout) {
    const int s = blockIdx.x, b = blockIdx.y;
    const int rowi = b * S_ + s;
    const int cnt = g_cnt[rowi];
    const int tid = threadIdx.x, lane = tid & 31, warp = tid >> 5;
    const size_t xoff = (size_t)rowi * D_;
    float* Arow = Aout + (size_t)rowi * S_;
    const int* crow = g_cand + (size_t)rowi * NCAND;

    float4 x4 = ((const float4*)(X + xoff))[tid];

    if (cnt <= 1) {
        const int t = crow[0];
        if (tid == 0) Arow[t] = 1.0f;
        const __half2* vr = (const __half2*)(g_Vh + ((size_t)b * S_ + t) * D_) + tid * 2;
        float2 p0 = __half22float2(vr[0]);
        float2 p1 = __half22float2(vr[1]);
        float4 o = make_float4(x4.x + p0.x, x4.y + p0.y, x4.z + p1.x, x4.w + p1.y);
        ((float4*)(Yout + xoff))[tid] = o;
        return;
    }

    __shared__ float qrow[D_];
    __shared__ float av[NCAND];
    __shared__ float red[8];
    const int slot = g_slot[rowi];
    ((float4*)qrow)[tid] = ((const float4*)(g_Qc + (size_t)slot * D_))[tid];
    __syncthreads();
    const float* Xb = X + (size_t)b * S_ * D_;

    float y0 = 0.f, y1 = 0.f, y2 = 0.f, y3 = 0.f;

    if (cnt != 255) {
        for (int ci = warp; ci < cnt; ci += 8) {
            const float* xr = Xb + (size_t)crow[ci] * D_;
            float d = 0.f;
            for (int k = lane; k < D_; k += 32) d += qrow[k] * xr[k];
#pragma unroll
            for (int o = 16; o > 0; o >>= 1) d += __shfl_xor_sync(0xffffffffu, d, o);
            if (lane == 0) av[ci] = d * 32.0f;
        }
        __syncthreads();
        if (tid == 0) {
            float mm = -3.0e38f;
            for (int ci = 0; ci < cnt; ci++) mm = fmaxf(mm, av[ci]);
            float Z = 0.f;
            for (int ci = 0; ci < cnt; ci++) { av[ci] = expf(av[ci] - mm); Z += av[ci]; }
            const float inv = 1.0f / Z;
            for (int ci = 0; ci < cnt; ci++) {
                av[ci] *= inv;
                Arow[crow[ci]] = av[ci];
            }
        }
        __syncthreads();
        for (int ci = 0; ci < cnt; ci++) {
            const float a = av[ci];
            const __half2* vr = (const __half2*)(g_Vh + ((size_t)b * S_ + crow[ci]) * D_) + tid * 2;
            float2 p0 = __half22float2(vr[0]);
            float2 p1 = __half22float2(vr[1]);
            y0 += a * p0.x; y1 += a * p0.y; y2 += a * p1.x; y3 += a * p1.y;
        }
    } else {
        const int len = s + 1;
        for (int t = warp; t < len; t += 8) {
            const float* xr = Xb + (size_t)t * D_;
            float d = 0.f;
            for (int k = lane; k < D_; k += 32) d += qrow[k] * xr[k];
#pragma unroll
            for (int o = 16; o > 0; o >>= 1) d += __shfl_xor_sync(0xffffffffu, d, o);
            if (lane == 0) Arow[t] = d * 32.0f;
        }
        __syncthreads();
        float mm = -3.0e38f;
        for (int j = tid; j < len; j += 256) mm = fmaxf(mm, Arow[j]);
#pragma unroll
        for (int o = 16; o > 0; o >>= 1) mm = fmaxf(mm, __shfl_xor_sync(0xffffffffu, mm, o));
        if (lane == 0) red[warp] = mm;
        __syncthreads();
        mm = red[lane & 7];
#pragma unroll
        for (int o = 4; o > 0; o >>= 1) mm = fmaxf(mm, __shfl_xor_sync(0xffffffffu, mm, o));
        float Z = 0.f;
        for (int j = tid; j < len; j += 256) Z += expf(Arow[j] - mm);
#pragma unroll
        for (int o = 16; o > 0; o >>= 1) Z += __shfl_xor_sync(0xffffffffu, Z, o);
        if (lane == 0) red[warp] = Z;
        __syncthreads();
        Z = red[lane & 7];
#pragma unroll
        for (int o = 4; o > 0; o >>= 1) Z += __shfl_xor_sync(0xffffffffu, Z, o);
        const float inv = 1.0f / Z;
        __syncthreads();
        for (int j = tid; j < len; j += 256) Arow[j] = expf(Arow[j] - mm) * inv;
        __syncthreads();
        for (int t = 0; t < len; t++) {
            const float a = Arow[t];
            if (a > 1e-30f) {
                const __half2* vr = (const __half2*)(g_Vh + ((size_t)b * S_ + t) * D_) + tid * 2;
                float2 p0 = __half22float2(vr[0]);
                float2 p1 = __half22float2(vr[1]);
                y0 += a * p0.x; y1 += a * p0.y; y2 += a * p1.x; y3 += a * p1.y;
            }
        }
    }
    float4 o = make_float4(x4.x + y0, x4.y + y1, x4.z + y2, x4.w + y3);
    ((float4*)(Yout + xoff))[tid] = o;
}

// ---------------------------------------------------------------------------
extern "C" void kernel_launch(void* const* d_in, const int* in_sizes, int n_in,
                              void* d_out, int out_size) {
    const float* X   = (const float*)d_in[0];
    const float* WQK = (const float*)d_in[2];
    const float* WOV = (const float*)d_in[3];
    float* out = (float*)d_out;

    const size_t nY = (size_t)M1 * D_;
    const size_t nA = (size_t)B_ * S_ * S_;
    float* Aout;
    if ((size_t)out_size >= nY + nA) {
        Aout = out + nY;
    } else {
        void* p = nullptr;
        cudaGetSymbolAddress(&p, g_Afallback);
        Aout = (float*)p;
    }

    static bool attrs_set = false;
    if (!attrs_set) {
        cudaFuncSetAttribute(k_qv,     cudaFuncAttributeMaxDynamicSharedMemorySize, SMEM_NT);
        cudaFuncSetAttribute(k_scores, cudaFuncAttributeMaxDynamicSharedMemorySize, SMEM_NT);
        cudaFuncSetAttribute(k_qfix,   cudaFuncAttributeMaxDynamicSharedMemorySize, SMEM_HILO);
        attrs_set = true;
    }

    // 1) conversions (merged; resets g_nfix)
    k_cvt<<<576, 256>>>((const float4*)X, (const float4*)WQK, (const float4*)WOV);
    // 2) Q (1-pass bf16) and V (1-pass fp16)
    k_qv<<<dim3(D_ / 128, M1 / 128, 2), 128, SMEM_NT>>>();
    // 3) scores GEMM -> fp16 logit scratch; whole A zeroed here
    k_scores<<<dim3(S_ / 128, S_ / 128, B_), 128, SMEM_NT>>>(Aout);
    // 4) candidate finder (reads fp16 scratch; no A traffic)
    k_softmax<<<dim3(S_, B_), 256>>>();
    // 5) exact Q for flagged rows (indirect 3-pass GEMM)
    k_qfix<<<dim3(D_ / 128, M1 / 128), 128, SMEM_HILO>>>();
    // 6) exact softmax + out = X + A.V in one pass
    k_finish<<<dim3(S_, B_), 256>>>(X, out, Aout);
}